// round 5
// baseline (speedup 1.0000x reference)
#include <cuda_runtime.h>
#include <cstdint>

#define H   2048
#define I   1408
#define E   8
#define T   512
#define I2  2816   // 2*I
#define IW  704    // I/2: act row width in uint32 (bf16 pairs)

// ---------------- device scratch (no allocations allowed) ----------------
__device__ int   g_cnt[E];
__device__ int   g_tok[E][T];
__device__ float g_cw [E][T];
__device__ __align__(16) uint32_t g_act_hi[(size_t)E * T * IW];  // bf16 pairs
__device__ __align__(16) uint32_t g_act_lo[(size_t)E * T * IW];

// ---------------- helpers ----------------
__device__ __forceinline__ uint32_t smem_u32(const void* p) {
    uint32_t a;
    asm("{ .reg .u64 t; cvta.to.shared.u64 t, %1; cvt.u32.u64 %0, t; }" : "=r"(a) : "l"(p));
    return a;
}
__device__ __forceinline__ uint32_t packbf(float lo, float hi) {
    uint32_t r;
    asm("cvt.rn.bf16x2.f32 %0, %1, %2;" : "=r"(r) : "f"(hi), "f"(lo));
    return r;
}
__device__ __forceinline__ void split4(float4 v, uint32_t& h0, uint32_t& h1,
                                       uint32_t& l0, uint32_t& l1) {
    h0 = packbf(v.x, v.y);
    h1 = packbf(v.z, v.w);
    float fx = __uint_as_float(h0 << 16), fy = __uint_as_float(h0 & 0xFFFF0000u);
    float fz = __uint_as_float(h1 << 16), fw = __uint_as_float(h1 & 0xFFFF0000u);
    l0 = packbf(v.x - fx, v.y - fy);
    l1 = packbf(v.z - fz, v.w - fw);
}
__device__ __forceinline__ void ldsm4(uint32_t* r, uint32_t a) {
    asm volatile("ldmatrix.sync.aligned.m8n8.x4.shared.b16 {%0,%1,%2,%3}, [%4];"
        : "=r"(r[0]), "=r"(r[1]), "=r"(r[2]), "=r"(r[3]) : "r"(a));
}
__device__ __forceinline__ void mma_bf(float* d, const uint32_t* a, uint32_t b0, uint32_t b1) {
    asm volatile("mma.sync.aligned.m16n8k16.row.col.f32.bf16.bf16.f32 "
        "{%0,%1,%2,%3}, {%4,%5,%6,%7}, {%8,%9}, {%0,%1,%2,%3};"
        : "+f"(d[0]), "+f"(d[1]), "+f"(d[2]), "+f"(d[3])
        : "r"(a[0]), "r"(a[1]), "r"(a[2]), "r"(a[3]), "r"(b0), "r"(b1));
}

// ---------------- reset ----------------
__global__ void k_reset(float* __restrict__ out) {
    int idx = blockIdx.x * blockDim.x + threadIdx.x;
    if (idx < T * H) out[idx] = 0.f;
    if (idx < E) g_cnt[idx] = 0;
}

// ---------------- router ----------------
__global__ void k_router(const float* __restrict__ x, const float* __restrict__ wg) {
    const int t = blockIdx.x, tid = threadIdx.x, w = tid >> 5, lane = tid & 31;
    const float* xr = x  + (size_t)t * H;
    const float* gr = wg + (size_t)w * H;
    float s = 0.f;
    for (int i = lane * 4; i < H; i += 128) {
        float4 xv = *(const float4*)(xr + i);
        float4 gv = *(const float4*)(gr + i);
        s += xv.x * gv.x + xv.y * gv.y + xv.z * gv.z + xv.w * gv.w;
    }
    #pragma unroll
    for (int o = 16; o; o >>= 1) s += __shfl_xor_sync(0xffffffffu, s, o);
    __shared__ float lg[E];
    if (lane == 0) lg[w] = s;
    __syncthreads();
    if (tid == 0) {
        float mx = lg[0];
        #pragma unroll
        for (int e = 1; e < E; e++) mx = fmaxf(mx, lg[e]);
        float ex[E];
        #pragma unroll
        for (int e = 0; e < E; e++) ex[e] = expf(lg[e] - mx);
        int i0 = 0;
        #pragma unroll
        for (int e = 1; e < E; e++) if (ex[e] > ex[i0]) i0 = e;
        int i1 = (i0 == 0) ? 1 : 0;
        #pragma unroll
        for (int e = 0; e < E; e++) if (e != i0 && ex[e] > ex[i1]) i1 = e;
        float s0 = ex[i0], s1 = ex[i1], inv = 1.f / (s0 + s1);
        int p0 = atomicAdd(&g_cnt[i0], 1);
        g_tok[i0][p0] = t;  g_cw[i0][p0] = s0 * inv;
        int p1 = atomicAdd(&g_cnt[i1], 1);
        g_tok[i1][p1] = t;  g_cw[i1][p1] = s1 * inv;
    }
}

// 32x32 warp tile compute on hi/lo split smem tiles (rows 128B: hi[0,64) lo[64,128))
#define COMPUTE32(aoff_, boff_)                                                 \
    {                                                                           \
        _Pragma("unroll")                                                       \
        for (int kk = 0; kk < 2; kk++) {                                        \
            uint32_t Ah[2][4], Al[2][4], Bh[2][4], Bl[2][4];                    \
            _Pragma("unroll")                                                   \
            for (int mt = 0; mt < 2; mt++) {                                    \
                uint32_t off = a_swb + mt * 2048;                               \
                ldsm4(Ah[mt], (aoff_) + (off ^ (kk << 5)));                     \
                ldsm4(Al[mt], (aoff_) + (off ^ (kk << 5) ^ 64));                \
            }                                                                   \
            _Pragma("unroll")                                                   \
            for (int n2 = 0; n2 < 2; n2++) {                                    \
                uint32_t off = b_swb + n2 * 2048;                               \
                ldsm4(Bh[n2], (boff_) + (off ^ (kk << 5)));                     \
                ldsm4(Bl[n2], (boff_) + (off ^ (kk << 5) ^ 64));                \
            }                                                                   \
            _Pragma("unroll")                                                   \
            for (int mt = 0; mt < 2; mt++)                                      \
                _Pragma("unroll")                                               \
                for (int n2 = 0; n2 < 2; n2++) {                                \
                    mma_bf(acc[mt][2 * n2],     Ah[mt], Bh[n2][0], Bh[n2][1]);  \
                    mma_bf(acc[mt][2 * n2 + 1], Ah[mt], Bh[n2][2], Bh[n2][3]);  \
                }                                                               \
            _Pragma("unroll")                                                   \
            for (int mt = 0; mt < 2; mt++)                                      \
                _Pragma("unroll")                                               \
                for (int n2 = 0; n2 < 2; n2++) {                                \
                    mma_bf(acc[mt][2 * n2],     Ah[mt], Bl[n2][0], Bl[n2][1]);  \
                    mma_bf(acc[mt][2 * n2 + 1], Ah[mt], Bl[n2][2], Bl[n2][3]);  \
                }                                                               \
            _Pragma("unroll")                                                   \
            for (int mt = 0; mt < 2; mt++)                                      \
                _Pragma("unroll")                                               \
                for (int n2 = 0; n2 < 2; n2++) {                                \
                    mma_bf(acc[mt][2 * n2],     Al[mt], Bh[n2][0], Bh[n2][1]);  \
                    mma_bf(acc[mt][2 * n2 + 1], Al[mt], Bh[n2][2], Bh[n2][3]);  \
                }                                                               \
        }                                                                       \
    }

// ---------------- GEMM1: act = silu(x@Wg^T)*(x@Wu^T) ----------------
// 256 thr, 2 CTAs/SM; block 128m x 64n(32 gate + 32 up), BK=32; warp grid 4m x 2n.
__global__ void __launch_bounds__(256, 2) k_gemm1(const float* __restrict__ x,
                                                  const float* __restrict__ w1) {
    const int e = blockIdx.z, cnt = g_cnt[e];
    const int m0 = blockIdx.y * 128;
    if (m0 >= cnt) return;
    const int n0 = blockIdx.x * 32;   // gate col base (up at I + n0)

    extern __shared__ char sm[];
    const uint32_t sbase = smem_u32(sm);
    __shared__ int s_tok[128];

    const int tid = threadIdx.x, lane = tid & 31, wid = tid >> 5;
    if (tid < 128) { int r = m0 + tid; if (r >= cnt) r = cnt - 1; s_tok[tid] = g_tok[e][r]; }
    __syncthreads();

    // A loader: 2 thr/row, 16 floats each
    const int lrow = tid >> 1, lkq = (tid & 1) * 16;
    const float* aptr = x + (size_t)s_tok[lrow] * H + lkq;
    const uint32_t s_swA = (uint32_t)(lrow * 128 + lkq * 2) ^ (((uint32_t)lrow & 7) << 4);
    // B loader: 64 rows (32 gate + 32 up), 4 thr/row, 8 floats each
    const int brow = tid >> 2, bq = tid & 3;
    const int wrow = (brow < 32) ? (n0 + brow) : (I + n0 + brow - 32);
    const float* bptr = w1 + ((size_t)e * I2 + wrow) * H + bq * 8;
    const uint32_t s_swB = ((uint32_t)(brow * 128 + bq * 16)) ^ (((uint32_t)brow & 7) << 4);

    const int wm = (wid & 3) * 32, wn = (wid >> 2) * 32;
    const uint32_t a_row = wm + (lane & 15);
    const uint32_t a_swb = (a_row * 128 + ((lane >> 4) << 4)) ^ ((a_row & 7) << 4);
    const uint32_t b_row = wn + (lane & 7) + ((lane >> 4) << 3);
    const uint32_t b_swb = (b_row * 128 + (((lane >> 3) & 1) << 4)) ^ ((b_row & 7) << 4);

    float acc[2][4][4] = {};
    float4 av[4], bv[2];
    #pragma unroll
    for (int i = 0; i < 4; i++) av[i] = *(const float4*)(aptr + 4 * i);
    bv[0] = *(const float4*)(bptr);  bv[1] = *(const float4*)(bptr + 4);
    {   // STS stage 0
        char* sA = sm;  char* sB = sm + 0x4000;
        #pragma unroll
        for (int i = 0; i < 4; i++) {
            uint32_t h0, h1, l0, l1, o = s_swA ^ (i << 3);
            split4(av[i], h0, h1, l0, l1);
            *(uint2*)(sA + o) = make_uint2(h0, h1);
            *(uint2*)(sA + (o ^ 64)) = make_uint2(l0, l1);
        }
        #pragma unroll
        for (int i = 0; i < 2; i++) {
            uint32_t h0, h1, l0, l1, o = s_swB ^ (i << 3);
            split4(bv[i], h0, h1, l0, l1);
            *(uint2*)(sB + o) = make_uint2(h0, h1);
            *(uint2*)(sB + (o ^ 64)) = make_uint2(l0, l1);
        }
    }
    __syncthreads();

    const int KT = H / 32;
    for (int kt = 0; kt < KT; kt++) {
        const int b = kt & 1;
        if (kt + 1 < KT) {
            const int k0 = (kt + 1) * 32;
            #pragma unroll
            for (int i = 0; i < 4; i++) av[i] = *(const float4*)(aptr + k0 + 4 * i);
            bv[0] = *(const float4*)(bptr + k0);  bv[1] = *(const float4*)(bptr + k0 + 4);
        }
        const uint32_t aoff = sbase + b * 0x6000;
        const uint32_t boff = aoff + 0x4000;
        COMPUTE32(aoff, boff);
        if (kt + 1 < KT) {   // STS next tile into other buffer; one sync per iter
            char* sA = sm + (b ^ 1) * 0x6000;  char* sB = sA + 0x4000;
            #pragma unroll
            for (int i = 0; i < 4; i++) {
                uint32_t h0, h1, l0, l1, o = s_swA ^ (i << 3);
                split4(av[i], h0, h1, l0, l1);
                *(uint2*)(sA + o) = make_uint2(h0, h1);
                *(uint2*)(sA + (o ^ 64)) = make_uint2(l0, l1);
            }
            #pragma unroll
            for (int i = 0; i < 2; i++) {
                uint32_t h0, h1, l0, l1, o = s_swB ^ (i << 3);
                split4(bv[i], h0, h1, l0, l1);
                *(uint2*)(sB + o) = make_uint2(h0, h1);
                *(uint2*)(sB + (o ^ 64)) = make_uint2(l0, l1);
            }
        }
        __syncthreads();
    }

    // epilogue: stage D [128][66], recombine gate/up, split, store act
    float* stg = (float*)sm;
    #pragma unroll
    for (int mt = 0; mt < 2; mt++)
        #pragma unroll
        for (int nt = 0; nt < 4; nt++) {
            int r = wm + mt * 16 + (lane >> 2);
            int c = wn + nt * 8 + (lane & 3) * 2;
            stg[r * 66 + c]           = acc[mt][nt][0];
            stg[r * 66 + c + 1]       = acc[mt][nt][1];
            stg[(r + 8) * 66 + c]     = acc[mt][nt][2];
            stg[(r + 8) * 66 + c + 1] = acc[mt][nt][3];
        }
    __syncthreads();
    const int erow = tid >> 1, grow = m0 + erow;
    if (grow < cnt) {
        const int pb = (tid & 1) * 8;
        uint32_t hw[8], lw[8];
        #pragma unroll
        for (int j = 0; j < 8; j++) {
            int p = pb + j;
            float g0 = stg[erow * 66 + 2 * p],      g1 = stg[erow * 66 + 2 * p + 1];
            float u0 = stg[erow * 66 + 32 + 2 * p], u1 = stg[erow * 66 + 33 + 2 * p];
            float a0 = g0 / (1.f + __expf(-g0)) * u0;
            float a1 = g1 / (1.f + __expf(-g1)) * u1;
            uint32_t hh = packbf(a0, a1);
            hw[j] = hh;
            lw[j] = packbf(a0 - __uint_as_float(hh << 16),
                           a1 - __uint_as_float(hh & 0xFFFF0000u));
        }
        size_t base = ((size_t)e * T + grow) * IW + blockIdx.x * 16 + pb;
        *(uint4*)(g_act_hi + base)     = make_uint4(hw[0], hw[1], hw[2], hw[3]);
        *(uint4*)(g_act_hi + base + 4) = make_uint4(hw[4], hw[5], hw[6], hw[7]);
        *(uint4*)(g_act_lo + base)     = make_uint4(lw[0], lw[1], lw[2], lw[3]);
        *(uint4*)(g_act_lo + base + 4) = make_uint4(lw[4], lw[5], lw[6], lw[7]);
    }
}

// ---------------- GEMM2: out[tok] += cw * (act @ W2^T) ----------------
// 512 thr (16 warps); block 128x128, BK=32; warp grid 4m x 4n, warp tile 32x32.
__global__ void __launch_bounds__(512, 1) k_gemm2(const float* __restrict__ w2,
                                                  float* __restrict__ out) {
    const int e = blockIdx.z, cnt = g_cnt[e];
    const int m0 = blockIdx.y * 128;
    if (m0 >= cnt) return;
    const int n0 = blockIdx.x * 128;

    extern __shared__ char sm[];
    const uint32_t sbase = smem_u32(sm);
    __shared__ int   s_tok[128];
    __shared__ float s_cw [128];

    const int tid = threadIdx.x, lane = tid & 31, wid = tid >> 5;
    if (tid < 128) {
        int r = m0 + tid;
        int rr = (r < cnt) ? r : (cnt - 1);
        s_tok[tid] = g_tok[e][rr];
        s_cw [tid] = (r < cnt) ? g_cw[e][r] : 0.f;
    }
    __syncthreads();

    // loader roles: warps 0-7 load A (bf16 act), warps 8-15 load B (w2 fp32)
    const bool isA = tid < 256;
    const int lrow = (tid & 255) >> 1, half = tid & 1;
    int ar = m0 + lrow; if (ar >= cnt) ar = cnt - 1;
    const uint32_t* ahp = g_act_hi + ((size_t)e * T + ar) * IW + half * 8;
    const uint32_t* alp = g_act_lo + ((size_t)e * T + ar) * IW + half * 8;
    const float* bptr = w2 + ((size_t)e * H + n0 + lrow) * I + half * 16;
    const uint32_t s_sw = (uint32_t)(lrow * 128 + half * 32) ^ (((uint32_t)lrow & 7) << 4);

    const int wm = (wid & 3) * 32, wn = (wid >> 2) * 32;
    const uint32_t a_row = wm + (lane & 15);
    const uint32_t a_swb = (a_row * 128 + ((lane >> 4) << 4)) ^ ((a_row & 7) << 4);
    const uint32_t b_row = wn + (lane & 7) + ((lane >> 4) << 3);
    const uint32_t b_swb = (b_row * 128 + (((lane >> 3) & 1) << 4)) ^ ((b_row & 7) << 4);

    float acc[2][4][4] = {};
    uint4 ah[2], al[2];
    float4 bv[4];
    if (isA) {
        ah[0] = *(const uint4*)(ahp);  ah[1] = *(const uint4*)(ahp + 4);
        al[0] = *(const uint4*)(alp);  al[1] = *(const uint4*)(alp + 4);
    } else {
        #pragma unroll
        for (int i = 0; i < 4; i++) bv[i] = *(const float4*)(bptr + 4 * i);
    }
    {   // STS stage 0
        char* sA = sm;  char* sB = sm + 0x4000;
        if (isA) {
            *(uint4*)(sA + s_sw)             = ah[0];
            *(uint4*)(sA + (s_sw ^ 16))      = ah[1];
            *(uint4*)(sA + (s_sw ^ 64))      = al[0];
            *(uint4*)(sA + (s_sw ^ 64 ^ 16)) = al[1];
        } else {
            #pragma unroll
            for (int i = 0; i < 4; i++) {
                uint32_t h0, h1, l0, l1, o = s_sw ^ (i << 3);
                split4(bv[i], h0, h1, l0, l1);
                *(uint2*)(sB + o) = make_uint2(h0, h1);
                *(uint2*)(sB + (o ^ 64)) = make_uint2(l0, l1);
            }
        }
    }
    __syncthreads();

    const int KT = I / 32;
    for (int kt = 0; kt < KT; kt++) {
        const int b = kt & 1;
        if (kt + 1 < KT) {
            if (isA) {
                const int kw = (kt + 1) * 16;
                ah[0] = *(const uint4*)(ahp + kw);  ah[1] = *(const uint4*)(ahp + kw + 4);
                al[0] = *(const uint4*)(alp + kw);  al[1] = *(const uint4*)(alp + kw + 4);
            } else {
                const int k0 = (kt + 1) * 32;
                #pragma unroll
                for (int i = 0; i < 4; i++) bv[i] = *(const float4*)(bptr + k0 + 4 * i);
            }
        }
        const uint32_t aoff = sbase + b * 0x8000;
        const uint32_t boff = aoff + 0x4000;
        COMPUTE32(aoff, boff);
        if (kt + 1 < KT) {
            char* sA = sm + (b ^ 1) * 0x8000;  char* sB = sA + 0x4000;
            if (isA) {
                *(uint4*)(sA + s_sw)             = ah[0];
                *(uint4*)(sA + (s_sw ^ 16))      = ah[1];
                *(uint4*)(sA + (s_sw ^ 64))      = al[0];
                *(uint4*)(sA + (s_sw ^ 64 ^ 16)) = al[1];
            } else {
                #pragma unroll
                for (int i = 0; i < 4; i++) {
                    uint32_t h0, h1, l0, l1, o = s_sw ^ (i << 3);
                    split4(bv[i], h0, h1, l0, l1);
                    *(uint2*)(sB + o) = make_uint2(h0, h1);
                    *(uint2*)(sB + (o ^ 64)) = make_uint2(l0, l1);
                }
            }
        }
        __syncthreads();
    }

    // epilogue: scale + atomicAdd (each out element receives exactly 2 adds total)
    #pragma unroll
    for (int mt = 0; mt < 2; mt++)
        #pragma unroll
        for (int nt = 0; nt < 4; nt++) {
            int r = wm + mt * 16 + (lane >> 2);
            int c = n0 + wn + nt * 8 + (lane & 3) * 2;
            if (m0 + r < cnt) {
                float cw = s_cw[r];
                float* op = out + (size_t)s_tok[r] * H + c;
                atomicAdd(op,     acc[mt][nt][0] * cw);
                atomicAdd(op + 1, acc[mt][nt][1] * cw);
            }
            if (m0 + r + 8 < cnt) {
                float cw = s_cw[r + 8];
                float* op = out + (size_t)s_tok[r + 8] * H + c;
                atomicAdd(op,     acc[mt][nt][2] * cw);
                atomicAdd(op + 1, acc[mt][nt][3] * cw);
            }
        }
}

// ---------------- launch ----------------
extern "C" void kernel_launch(void* const* d_in, const int* in_sizes, int n_in,
                              void* d_out, int out_size) {
    const float* x  = (const float*)d_in[0];   // [T, H]
    const float* w1 = (const float*)d_in[1];   // [E, 2I, H]
    const float* w2 = (const float*)d_in[2];   // [E, H, I]
    const float* wg = (const float*)d_in[3];   // [E, H]
    float* out = (float*)d_out;                // [T, 1, H]

    cudaFuncSetAttribute(k_gemm1, cudaFuncAttributeMaxDynamicSharedMemorySize, 0xC000);
    cudaFuncSetAttribute(k_gemm2, cudaFuncAttributeMaxDynamicSharedMemorySize, 0x10000);

    k_reset<<<(T * H + 255) / 256, 256>>>(out);
    k_router<<<T, 256>>>(x, wg);
    k_gemm1<<<dim3(I / 32, (T + 127) / 128, E), 256, 0xC000>>>(x, w1);
    k_gemm2<<<dim3(H / 128, (T + 127) / 128, E), 512, 0x10000>>>(w2, out);
}

// round 6
// speedup vs baseline: 1.2756x; 1.2756x over previous
#include <cuda_runtime.h>
#include <cstdint>

#define H   2048
#define I   1408
#define E   8
#define T   512
#define I2  2816   // 2*I
#define IW  704    // I/2: act row width in uint32 (bf16 pairs)
#define HW  1024   // H/2: x row width in uint32 (bf16 pairs)

// smem layout (dynamic, per CTA): 3 A stages + 2 B buffers, 16KB each
#define ASTG(s) ((s) * 0x4000)
#define BBUF(b) (0xC000 + (b) * 0x4000)
#define SMEMSZ  0x14000   // 80 KB

// ---------------- device scratch (no allocations allowed) ----------------
__device__ int   g_cnt[E];
__device__ int   g_tok[E][T];
__device__ float g_cw [E][T];
__device__ __align__(16) uint32_t g_act_hi[(size_t)E * T * IW];
__device__ __align__(16) uint32_t g_act_lo[(size_t)E * T * IW];
__device__ __align__(16) uint32_t g_x_hi[(size_t)T * HW];
__device__ __align__(16) uint32_t g_x_lo[(size_t)T * HW];

// ---------------- helpers ----------------
__device__ __forceinline__ uint32_t smem_u32(const void* p) {
    uint32_t a;
    asm("{ .reg .u64 t; cvta.to.shared.u64 t, %1; cvt.u32.u64 %0, t; }" : "=r"(a) : "l"(p));
    return a;
}
__device__ __forceinline__ uint32_t packbf(float lo, float hi) {
    uint32_t r;
    asm("cvt.rn.bf16x2.f32 %0, %1, %2;" : "=r"(r) : "f"(hi), "f"(lo));
    return r;
}
__device__ __forceinline__ void split4(float4 v, uint32_t& h0, uint32_t& h1,
                                       uint32_t& l0, uint32_t& l1) {
    h0 = packbf(v.x, v.y);
    h1 = packbf(v.z, v.w);
    float fx = __uint_as_float(h0 << 16), fy = __uint_as_float(h0 & 0xFFFF0000u);
    float fz = __uint_as_float(h1 << 16), fw = __uint_as_float(h1 & 0xFFFF0000u);
    l0 = packbf(v.x - fx, v.y - fy);
    l1 = packbf(v.z - fz, v.w - fw);
}
__device__ __forceinline__ void ldsm4(uint32_t* r, uint32_t a) {
    asm volatile("ldmatrix.sync.aligned.m8n8.x4.shared.b16 {%0,%1,%2,%3}, [%4];"
        : "=r"(r[0]), "=r"(r[1]), "=r"(r[2]), "=r"(r[3]) : "r"(a));
}
__device__ __forceinline__ void mma_bf(float* d, const uint32_t* a, uint32_t b0, uint32_t b1) {
    asm volatile("mma.sync.aligned.m16n8k16.row.col.f32.bf16.bf16.f32 "
        "{%0,%1,%2,%3}, {%4,%5,%6,%7}, {%8,%9}, {%0,%1,%2,%3};"
        : "+f"(d[0]), "+f"(d[1]), "+f"(d[2]), "+f"(d[3])
        : "r"(a[0]), "r"(a[1]), "r"(a[2]), "r"(a[3]), "r"(b0), "r"(b1));
}
#define CP16(d_, s_)  asm volatile("cp.async.cg.shared.global [%0], [%1], 16;" :: "r"(d_), "l"(s_))
#define CPCOMMIT()    asm volatile("cp.async.commit_group;" ::)
#define CPWAIT(n_)    asm volatile("cp.async.wait_group %0;" :: "n"(n_))

// ---------------- reset ----------------
__global__ void k_reset(float* __restrict__ out) {
    int idx = blockIdx.x * blockDim.x + threadIdx.x;
    if (idx < T * H) out[idx] = 0.f;
    if (idx < E) g_cnt[idx] = 0;
}

// ---------------- split x into bf16 hi/lo ----------------
__global__ void k_splitx(const float* __restrict__ x) {
    int idx = blockIdx.x * blockDim.x + threadIdx.x;   // float4 index
    float4 v = *((const float4*)x + idx);
    uint32_t h0, h1, l0, l1;
    split4(v, h0, h1, l0, l1);
    *(uint2*)(g_x_hi + idx * 2) = make_uint2(h0, h1);
    *(uint2*)(g_x_lo + idx * 2) = make_uint2(l0, l1);
}

// ---------------- router ----------------
__global__ void k_router(const float* __restrict__ x, const float* __restrict__ wg) {
    const int t = blockIdx.x, tid = threadIdx.x, w = tid >> 5, lane = tid & 31;
    const float* xr = x  + (size_t)t * H;
    const float* gr = wg + (size_t)w * H;
    float s = 0.f;
    for (int i = lane * 4; i < H; i += 128) {
        float4 xv = *(const float4*)(xr + i);
        float4 gv = *(const float4*)(gr + i);
        s += xv.x * gv.x + xv.y * gv.y + xv.z * gv.z + xv.w * gv.w;
    }
    #pragma unroll
    for (int o = 16; o; o >>= 1) s += __shfl_xor_sync(0xffffffffu, s, o);
    __shared__ float lg[E];
    if (lane == 0) lg[w] = s;
    __syncthreads();
    if (tid == 0) {
        float mx = lg[0];
        #pragma unroll
        for (int e = 1; e < E; e++) mx = fmaxf(mx, lg[e]);
        float ex[E];
        #pragma unroll
        for (int e = 0; e < E; e++) ex[e] = expf(lg[e] - mx);
        int i0 = 0;
        #pragma unroll
        for (int e = 1; e < E; e++) if (ex[e] > ex[i0]) i0 = e;
        int i1 = (i0 == 0) ? 1 : 0;
        #pragma unroll
        for (int e = 0; e < E; e++) if (e != i0 && ex[e] > ex[i1]) i1 = e;
        float s0 = ex[i0], s1 = ex[i1], inv = 1.f / (s0 + s1);
        int p0 = atomicAdd(&g_cnt[i0], 1);
        g_tok[i0][p0] = t;  g_cw[i0][p0] = s0 * inv;
        int p1 = atomicAdd(&g_cnt[i1], 1);
        g_tok[i1][p1] = t;  g_cw[i1][p1] = s1 * inv;
    }
}

// 64m x 32n warp tile, 3-pass hi/lo bf16; tiles: 128B rows = hi[0,64) | lo[64,128)
#define COMPUTE()                                                               \
    {                                                                           \
        _Pragma("unroll")                                                       \
        for (int kk = 0; kk < 2; kk++) {                                        \
            uint32_t Bh[2][4], Bl[2][4];                                        \
            _Pragma("unroll")                                                   \
            for (int n2 = 0; n2 < 2; n2++) {                                    \
                uint32_t ob = (b_swb + n2 * 2048) ^ (kk << 5);                  \
                ldsm4(Bh[n2], boff + ob);                                       \
                ldsm4(Bl[n2], boff + (ob ^ 64));                                \
            }                                                                   \
            _Pragma("unroll")                                                   \
            for (int mt = 0; mt < 4; mt++) {                                    \
                uint32_t Ah[4], Al[4];                                          \
                uint32_t oa = (a_swb + mt * 2048) ^ (kk << 5);                  \
                ldsm4(Ah, aoff + oa);                                           \
                ldsm4(Al, aoff + (oa ^ 64));                                    \
                _Pragma("unroll")                                               \
                for (int n2 = 0; n2 < 2; n2++) {                                \
                    mma_bf(acc[mt][2 * n2],     Ah, Bh[n2][0], Bh[n2][1]);      \
                    mma_bf(acc[mt][2 * n2 + 1], Ah, Bh[n2][2], Bh[n2][3]);      \
                }                                                               \
                _Pragma("unroll")                                               \
                for (int n2 = 0; n2 < 2; n2++) {                                \
                    mma_bf(acc[mt][2 * n2],     Ah, Bl[n2][0], Bl[n2][1]);      \
                    mma_bf(acc[mt][2 * n2 + 1], Ah, Bl[n2][2], Bl[n2][3]);      \
                }                                                               \
                _Pragma("unroll")                                               \
                for (int n2 = 0; n2 < 2; n2++) {                                \
                    mma_bf(acc[mt][2 * n2],     Al, Bh[n2][0], Bh[n2][1]);      \
                    mma_bf(acc[mt][2 * n2 + 1], Al, Bh[n2][2], Bh[n2][3]);      \
                }                                                               \
            }                                                                   \
        }                                                                       \
    }

#define ISSUE_A(kt_)                                                            \
    do {                                                                        \
        if ((kt_) < KT) {                                                       \
            const char* sh = (const char*)(arow_hi + (kt_) * 16 + h * 8);       \
            const char* sl = (const char*)(arow_lo + (kt_) * 16 + h * 8);       \
            uint32_t d = sbase + (((kt_) % 3) << 14) + a_dst0;                  \
            CP16(d,             sh);                                            \
            CP16(d ^ 16,        sh + 16);                                       \
            CP16(d ^ 64,        sl);                                            \
            CP16(d ^ 64 ^ 16,   sl + 16);                                       \
        }                                                                       \
        CPCOMMIT();                                                             \
    } while (0)

#define LDG_B(kt_)                                                              \
    { const float* p = bptr + (size_t)(kt_) * 32;                               \
      bv[0] = *(const float4*)p;       bv[1] = *(const float4*)(p + 4);         \
      bv[2] = *(const float4*)(p + 8); bv[3] = *(const float4*)(p + 12); }

#define STS_B(b_)                                                               \
    { char* s = sm + BBUF(b_);                                                  \
      _Pragma("unroll")                                                         \
      for (int i = 0; i < 4; i++) {                                             \
          uint32_t h0, h1, l0, l1, o = s_swB ^ (i << 3);                        \
          split4(bv[i], h0, h1, l0, l1);                                        \
          *(uint2*)(s + o)        = make_uint2(h0, h1);                         \
          *(uint2*)(s + (o ^ 64)) = make_uint2(l0, l1);                         \
      } }

// ---------------- GEMM1: act = silu(x@Wg^T)*(x@Wu^T) ----------------
// block 128m x 128n-tile (64 gate rows + 64 up rows -> 64 output cols), BK=32
__global__ void __launch_bounds__(256, 2) k_gemm1(const float* __restrict__ w1) {
    const int e = blockIdx.z, cnt = g_cnt[e];
    const int m0 = blockIdx.y * 128;
    if (m0 >= cnt) return;
    const int n0 = blockIdx.x * 64;

    extern __shared__ char sm[];
    const uint32_t sbase = smem_u32(sm);
    __shared__ int s_tok[128];

    const int tid = threadIdx.x, lane = tid & 31, wid = tid >> 5;
    if (tid < 128) { int r = m0 + tid; if (r >= cnt) r = cnt - 1; s_tok[tid] = g_tok[e][r]; }
    __syncthreads();

    // A cp.async: 2 thr/row
    const int lrow = tid >> 1, h = tid & 1;
    const uint32_t* arow_hi = g_x_hi + (size_t)s_tok[lrow] * HW;
    const uint32_t* arow_lo = g_x_lo + (size_t)s_tok[lrow] * HW;
    const uint32_t a_dst0 = ((uint32_t)(lrow * 128 + h * 32)) ^ (((uint32_t)lrow & 7) << 4);
    // B loader: 2 thr/row, 16 floats
    const int brow = tid >> 1, kq = (tid & 1) * 16;
    const int wrow = (brow < 64) ? (n0 + brow) : (I + n0 + brow - 64);
    const float* bptr = w1 + ((size_t)e * I2 + wrow) * H + kq;
    const uint32_t s_swB = ((uint32_t)(brow * 128 + kq * 2)) ^ (((uint32_t)brow & 7) << 4);
    // fragment bases
    const int wm = (wid & 1) * 64, wn = (wid >> 1) * 32;
    const uint32_t a_row = wm + (lane & 15);
    const uint32_t a_swb = (a_row * 128 + ((lane >> 4) << 4)) ^ ((a_row & 7) << 4);
    const uint32_t b_row = wn + (lane & 7) + ((lane >> 4) << 3);
    const uint32_t b_swb = (b_row * 128 + (((lane >> 3) & 1) << 4)) ^ ((b_row & 7) << 4);

    float acc[4][4][4] = {};
    float4 bv[4];
    const int KT = H / 32;

    ISSUE_A(0);
    ISSUE_A(1);
    LDG_B(0);
    STS_B(0);

    for (int kt = 0; kt < KT; kt++) {
        if (kt + 1 < KT) LDG_B(kt + 1);
        CPWAIT(1);
        __syncthreads();
        ISSUE_A(kt + 2);
        const uint32_t aoff = sbase + ((kt % 3) << 14);
        const uint32_t boff = sbase + 0xC000 + ((kt & 1) << 14);
        COMPUTE();
        if (kt + 1 < KT) STS_B((kt + 1) & 1);
    }

    // epilogue: stage D [128][132] f32, recombine gate/up, split, store act
    CPWAIT(0);
    __syncthreads();
    float* stg = (float*)sm;
    #pragma unroll
    for (int mt = 0; mt < 4; mt++)
        #pragma unroll
        for (int nt = 0; nt < 4; nt++) {
            int r = wm + mt * 16 + (lane >> 2);
            int c = wn + nt * 8 + (lane & 3) * 2;
            stg[r * 132 + c]           = acc[mt][nt][0];
            stg[r * 132 + c + 1]       = acc[mt][nt][1];
            stg[(r + 8) * 132 + c]     = acc[mt][nt][2];
            stg[(r + 8) * 132 + c + 1] = acc[mt][nt][3];
        }
    __syncthreads();
    const int erow = tid >> 1, grow = m0 + erow;
    if (grow < cnt) {
        const int pb = (tid & 1) * 16;
        uint32_t hw[16], lw[16];
        #pragma unroll
        for (int j = 0; j < 16; j++) {
            int p = pb + j;
            float g0 = stg[erow * 132 + 2 * p],      g1 = stg[erow * 132 + 2 * p + 1];
            float u0 = stg[erow * 132 + 64 + 2 * p], u1 = stg[erow * 132 + 65 + 2 * p];
            float a0 = g0 / (1.f + __expf(-g0)) * u0;
            float a1 = g1 / (1.f + __expf(-g1)) * u1;
            uint32_t hh = packbf(a0, a1);
            hw[j] = hh;
            lw[j] = packbf(a0 - __uint_as_float(hh << 16),
                           a1 - __uint_as_float(hh & 0xFFFF0000u));
        }
        size_t base = ((size_t)e * T + grow) * IW + (n0 >> 1) + pb;
        #pragma unroll
        for (int q = 0; q < 4; q++) {
            *(uint4*)(g_act_hi + base + 4 * q) = make_uint4(hw[4*q], hw[4*q+1], hw[4*q+2], hw[4*q+3]);
            *(uint4*)(g_act_lo + base + 4 * q) = make_uint4(lw[4*q], lw[4*q+1], lw[4*q+2], lw[4*q+3]);
        }
    }
}

// ---------------- GEMM2: out[tok] += cw * (act @ W2^T) ----------------
// block 128m x 128n, BK=32
__global__ void __launch_bounds__(256, 2) k_gemm2(const float* __restrict__ w2,
                                                  float* __restrict__ out) {
    const int e = blockIdx.z, cnt = g_cnt[e];
    const int m0 = blockIdx.y * 128;
    if (m0 >= cnt) return;
    const int n0 = blockIdx.x * 128;

    extern __shared__ char sm[];
    const uint32_t sbase = smem_u32(sm);
    __shared__ int   s_tok[128];
    __shared__ float s_cw [128];

    const int tid = threadIdx.x, lane = tid & 31, wid = tid >> 5;
    if (tid < 128) {
        int r = m0 + tid, rr = (r < cnt) ? r : (cnt - 1);
        s_tok[tid] = g_tok[e][rr];
        s_cw [tid] = (r < cnt) ? g_cw[e][r] : 0.f;
    }
    __syncthreads();

    const int lrow = tid >> 1, h = tid & 1;
    int ar = m0 + lrow; if (ar >= cnt) ar = cnt - 1;
    const uint32_t* arow_hi = g_act_hi + ((size_t)e * T + ar) * IW;
    const uint32_t* arow_lo = g_act_lo + ((size_t)e * T + ar) * IW;
    const uint32_t a_dst0 = ((uint32_t)(lrow * 128 + h * 32)) ^ (((uint32_t)lrow & 7) << 4);
    const int brow = tid >> 1, kq = (tid & 1) * 16;
    const float* bptr = w2 + ((size_t)e * H + n0 + brow) * I + kq;
    const uint32_t s_swB = ((uint32_t)(brow * 128 + kq * 2)) ^ (((uint32_t)brow & 7) << 4);

    const int wm = (wid & 1) * 64, wn = (wid >> 1) * 32;
    const uint32_t a_row = wm + (lane & 15);
    const uint32_t a_swb = (a_row * 128 + ((lane >> 4) << 4)) ^ ((a_row & 7) << 4);
    const uint32_t b_row = wn + (lane & 7) + ((lane >> 4) << 3);
    const uint32_t b_swb = (b_row * 128 + (((lane >> 3) & 1) << 4)) ^ ((b_row & 7) << 4);

    float acc[4][4][4] = {};
    float4 bv[4];
    const int KT = I / 32;

    ISSUE_A(0);
    ISSUE_A(1);
    LDG_B(0);
    STS_B(0);

    for (int kt = 0; kt < KT; kt++) {
        if (kt + 1 < KT) LDG_B(kt + 1);
        CPWAIT(1);
        __syncthreads();
        ISSUE_A(kt + 2);
        const uint32_t aoff = sbase + ((kt % 3) << 14);
        const uint32_t boff = sbase + 0xC000 + ((kt & 1) << 14);
        COMPUTE();
        if (kt + 1 < KT) STS_B((kt + 1) & 1);
    }
    CPWAIT(0);

    // epilogue: scale + atomicAdd (each out element receives exactly 2 adds total)
    #pragma unroll
    for (int mt = 0; mt < 4; mt++)
        #pragma unroll
        for (int nt = 0; nt < 4; nt++) {
            int r = wm + mt * 16 + (lane >> 2);
            int c = n0 + wn + nt * 8 + (lane & 3) * 2;
            if (m0 + r < cnt) {
                float cw = s_cw[r];
                float* op = out + (size_t)s_tok[r] * H + c;
                atomicAdd(op,     acc[mt][nt][0] * cw);
                atomicAdd(op + 1, acc[mt][nt][1] * cw);
            }
            if (m0 + r + 8 < cnt) {
                float cw = s_cw[r + 8];
                float* op = out + (size_t)s_tok[r + 8] * H + c;
                atomicAdd(op,     acc[mt][nt][2] * cw);
                atomicAdd(op + 1, acc[mt][nt][3] * cw);
            }
        }
}

// ---------------- launch ----------------
extern "C" void kernel_launch(void* const* d_in, const int* in_sizes, int n_in,
                              void* d_out, int out_size) {
    const float* x  = (const float*)d_in[0];   // [T, H]
    const float* w1 = (const float*)d_in[1];   // [E, 2I, H]
    const float* w2 = (const float*)d_in[2];   // [E, H, I]
    const float* wg = (const float*)d_in[3];   // [E, H]
    float* out = (float*)d_out;                // [T, 1, H]

    cudaFuncSetAttribute(k_gemm1, cudaFuncAttributeMaxDynamicSharedMemorySize, SMEMSZ);
    cudaFuncSetAttribute(k_gemm2, cudaFuncAttributeMaxDynamicSharedMemorySize, SMEMSZ);

    k_reset<<<(T * H + 255) / 256, 256>>>(out);
    k_splitx<<<(T * H / 4) / 256, 256>>>(x);
    k_router<<<T, 256>>>(x, wg);
    k_gemm1<<<dim3(I / 64, (T + 127) / 128, E), 256, SMEMSZ>>>(w1);
    k_gemm2<<<dim3(H / 128, (T + 127) / 128, E), 256, SMEMSZ>>>(w2, out);
}